// round 4
// baseline (speedup 1.0000x reference)
#include <cuda_runtime.h>
#include <cuda_fp16.h>
#include <math.h>
#include <stdint.h>

#define NTOK   1024
#define HID    768
#define FFN    3072
#define NEXP   8
#define SLOTS  (NTOK * 2)
#define TILE_M 128
#define TILE_N 128
#define TILE_K 64
#define MAXROWS 3072
#define MAX_MT (MAXROWS / TILE_M)   // 24
#define NT1    (FFN / TILE_N)       // 24
#define NT2    (HID / TILE_N)       // 6
#define STAGES 3

// per-stage: Ah 16K | Al 16K | Bh 16K | Bl 16K
#define OFF_AH  0
#define OFF_AL  16384
#define OFF_BH  32768
#define OFF_BL  49152
#define BUF_STRIDE 65536
#define SMEM_BYTES (STAGES * BUF_STRIDE)   // 192 KB

// ---------------- scratch ----------------------------------------------------
__device__ int   g_count[NEXP];
__device__ int   g_off[NEXP + 1];
__device__ int   g_tile_expert[MAX_MT];
__device__ int   g_slot_e[SLOTS];
__device__ int   g_slot_pos[SLOTS];
__device__ int   g_slot_row[SLOTS];
__device__ float g_slot_gate[SLOTS];
__device__ int   g_row_token[MAXROWS];
__device__ __half g_Xh[(size_t)MAXROWS * HID];
__device__ __half g_Xl[(size_t)MAXROWS * HID];
__device__ __half g_Hh[(size_t)MAXROWS * FFN];
__device__ __half g_Hl[(size_t)MAXROWS * FFN];
__device__ float  g_Y[(size_t)MAXROWS * HID];

// ---------------- helpers ----------------------------------------------------
__device__ __forceinline__ uint32_t smem_u32(const void* p) {
    uint32_t a;
    asm("{ .reg .u64 t; cvta.to.shared.u64 t, %1; cvt.u32.u64 %0, t; }" : "=r"(a) : "l"(p));
    return a;
}
__device__ __forceinline__ void ldsm_x4(uint32_t* r, uint32_t addr) {
    asm volatile("ldmatrix.sync.aligned.m8n8.x4.shared.b16 {%0,%1,%2,%3}, [%4];"
        : "=r"(r[0]), "=r"(r[1]), "=r"(r[2]), "=r"(r[3]) : "r"(addr));
}
__device__ __forceinline__ void ldsm_x4_t(uint32_t* r, uint32_t addr) {
    asm volatile("ldmatrix.sync.aligned.m8n8.x4.trans.shared.b16 {%0,%1,%2,%3}, [%4];"
        : "=r"(r[0]), "=r"(r[1]), "=r"(r[2]), "=r"(r[3]) : "r"(addr));
}
__device__ __forceinline__ void mma_f16(float* c, const uint32_t* a, uint32_t b0, uint32_t b1) {
    asm volatile("mma.sync.aligned.m16n8k16.row.col.f32.f16.f16.f32 "
        "{%0,%1,%2,%3}, {%4,%5,%6,%7}, {%8,%9}, {%0,%1,%2,%3};"
        : "+f"(c[0]), "+f"(c[1]), "+f"(c[2]), "+f"(c[3])
        : "r"(a[0]), "r"(a[1]), "r"(a[2]), "r"(a[3]), "r"(b0), "r"(b1));
}
#define NB_SYNC(id)   asm volatile("bar.sync %0, %1;"   :: "r"(id), "r"(256) : "memory")
#define NB_ARRIVE(id) asm volatile("bar.arrive %0, %1;" :: "r"(id), "r"(256) : "memory")

__device__ __forceinline__ uint32_t pack_hi2(float f0, float f1) {
    __half2 h = __floats2half2_rn(f0, f1);
    return *reinterpret_cast<uint32_t*>(&h);
}
__device__ __forceinline__ uint32_t pack_lo2(float f0, float f1, uint32_t hibits) {
    __half2 h = *reinterpret_cast<__half2*>(&hibits);
    float r0 = f0 - __half2float(h.x);
    float r1 = f1 - __half2float(h.y);
    __half2 l = __floats2half2_rn(r0, r1);
    return *reinterpret_cast<uint32_t*>(&l);
}
__device__ __forceinline__ float gelu_ex(float v) {
    return 0.5f * v * (1.f + erff(v * 0.70710678118654752f));
}
// swizzles: A [m][k] 128B rows; B [k][n] 256B rows
__device__ __forceinline__ uint32_t swA(uint32_t m, uint32_t kbyte) {
    return (m * 128 + kbyte) ^ ((m & 7) << 4);
}
__device__ __forceinline__ uint32_t swB(uint32_t k, uint32_t nbyte) {
    return (k * 256 + nbyte) ^ ((k & 7) << 4);
}

// ---------------- init / router / scan+scatter / xsplit ----------------------
__global__ void init_kernel() {
    int i = blockIdx.x * blockDim.x + threadIdx.x;
    if (i < MAXROWS) g_row_token[i] = -1;
    if (i < NEXP) g_count[i] = 0;
}

__global__ void router_kernel(const float* __restrict__ x,
                              const float* __restrict__ rw) {
    int gtid = blockIdx.x * blockDim.x + threadIdx.x;
    int tok  = gtid >> 5;
    int lane = gtid & 31;
    if (tok >= NTOK) return;
    const float* xp = x + tok * HID;
    float acc[NEXP];
#pragma unroll
    for (int e = 0; e < NEXP; e++) acc[e] = 0.f;
    for (int i = lane; i < HID; i += 32) {
        float xv = xp[i];
        const float* r = rw + i * NEXP;
#pragma unroll
        for (int e = 0; e < NEXP; e++) acc[e] += xv * r[e];
    }
#pragma unroll
    for (int off = 16; off; off >>= 1)
#pragma unroll
        for (int e = 0; e < NEXP; e++)
            acc[e] += __shfl_xor_sync(0xFFFFFFFFu, acc[e], off);
    if (lane == 0) {
        int i1 = 0; float v1 = acc[0];
#pragma unroll
        for (int e = 1; e < NEXP; e++)
            if (acc[e] > v1) { v1 = acc[e]; i1 = e; }
        int i2 = -1; float v2 = -INFINITY;
#pragma unroll
        for (int e = 0; e < NEXP; e++)
            if (e != i1 && acc[e] > v2) { v2 = acc[e]; i2 = e; }
        float g1 = 1.f / (1.f + expf(v2 - v1));
        float g2 = 1.f - g1;
        int s0 = tok * 2, s1 = s0 + 1;
        g_slot_e[s0] = i1; g_slot_gate[s0] = g1;
        g_slot_pos[s0] = atomicAdd(&g_count[i1], 1);
        g_slot_e[s1] = i2; g_slot_gate[s1] = g2;
        g_slot_pos[s1] = atomicAdd(&g_count[i2], 1);
    }
}

__global__ void scan_scatter_kernel() {
    int t = threadIdx.x;
    if (t == 0) {
        int off = 0;
        for (int e = 0; e < NEXP; e++) {
            g_off[e] = off;
            off += ((g_count[e] + TILE_M - 1) / TILE_M) * TILE_M;
        }
        g_off[NEXP] = off;
    }
    __syncthreads();
    if (t < MAX_MT) {
        int rbase = t * TILE_M;
        int ex = -1;
        for (int e = 0; e < NEXP; e++)
            if (rbase >= g_off[e] && rbase < g_off[e + 1]) { ex = e; break; }
        g_tile_expert[t] = ex;
    }
    for (int s = t; s < SLOTS; s += blockDim.x) {
        int e   = g_slot_e[s];
        int row = g_off[e] + g_slot_pos[s];
        g_slot_row[s]    = row;
        g_row_token[row] = s >> 1;
    }
}

// split X into fp16 hi/lo at its padded row; zero otherwise
__global__ void xsplit_kernel(const float* __restrict__ x) {
    int row = blockIdx.x;
    int t = threadIdx.x;                 // 192, 4 floats each
    int tok = g_row_token[row];
    float4 v = make_float4(0.f, 0.f, 0.f, 0.f);
    if (tok >= 0) v = ((const float4*)(x + (size_t)tok * HID))[t];
    uint32_t h0 = pack_hi2(v.x, v.y), h1 = pack_hi2(v.z, v.w);
    uint32_t l0 = pack_lo2(v.x, v.y, h0), l1 = pack_lo2(v.z, v.w, h1);
    ((uint2*)(g_Xh + (size_t)row * HID))[t] = make_uint2(h0, h1);
    ((uint2*)(g_Xl + (size_t)row * HID))[t] = make_uint2(l0, l1);
}

// ---------------- consumer chunk: warp tile 64x64 ----------------------------
__device__ __forceinline__ void consumer_chunk(uint32_t b32, int wm, int wn, int lane,
                                               float acc[4][8][4]) {
    uint32_t aAh = b32 + OFF_AH, aAl = b32 + OFF_AL;
    uint32_t aBh = b32 + OFF_BH, aBl = b32 + OFF_BL;
    uint32_t a_row = wm * 64 + (lane & 15);
    uint32_t a_kc  = (lane >> 4) * 16;
    uint32_t b_k   = (lane & 7) + ((lane >> 3) & 1) * 8;
    uint32_t b_nc  = (lane >> 4) * 16;
#pragma unroll
    for (int ks = 0; ks < 4; ks++) {
        uint32_t k0 = ks * 16;
        uint32_t ah[4][4], al[4][4];
#pragma unroll
        for (int mi = 0; mi < 4; mi++) {
            uint32_t addr = swA(a_row + mi * 16, k0 * 2 + a_kc);
            ldsm_x4(ah[mi], aAh + addr);
            ldsm_x4(al[mi], aAl + addr);
        }
#pragma unroll
        for (int g = 0; g < 4; g++) {
            uint32_t bh[4], bl[4];
            uint32_t addr = swB(k0 + b_k, (wn * 64 + g * 16) * 2 + b_nc);
            ldsm_x4_t(bh, aBh + addr);
            ldsm_x4_t(bl, aBl + addr);
#pragma unroll
            for (int mi = 0; mi < 4; mi++) {
                mma_f16(acc[mi][2 * g],     ah[mi], bh[0], bh[1]);
                mma_f16(acc[mi][2 * g + 1], ah[mi], bh[2], bh[3]);
                mma_f16(acc[mi][2 * g],     ah[mi], bl[0], bl[1]);
                mma_f16(acc[mi][2 * g + 1], ah[mi], bl[2], bl[3]);
                mma_f16(acc[mi][2 * g],     al[mi], bh[0], bh[1]);
                mma_f16(acc[mi][2 * g + 1], al[mi], bh[2], bh[3]);
            }
        }
    }
}

// ---------------- warp-specialized grouped GEMM ------------------------------
template <bool IS_FFN1>
__global__ void __launch_bounds__(256, 1) ffn_kernel(const float* __restrict__ w) {
    int mt = blockIdx.x, nt = blockIdx.y;
    int e = g_tile_expert[mt];
    if (e < 0) return;

    extern __shared__ char smem[];
    uint32_t sbase = smem_u32(smem);
    int tid = threadIdx.x, wid = tid >> 5, lane = tid & 31;
    int rbase = mt * TILE_M;

    const int NC  = IS_FFN1 ? (HID / TILE_K) : (FFN / TILE_K);
    const int LDA = IS_FFN1 ? HID : FFN;
    const int LDB = IS_FFN1 ? FFN : HID;

    if (wid >= 4) {
        // ---------------- producer ----------------
        int p = tid - 128;                 // 0..127
        const __half* ah_row = (IS_FFN1 ? g_Xh : g_Hh) + (size_t)(rbase + p) * LDA;
        const __half* al_row = (IS_FFN1 ? g_Xl : g_Hl) + (size_t)(rbase + p) * LDA;
        int bk = p >> 1, bnh = p & 1;
        const float* bsrc = w + (size_t)e * HID * FFN + (size_t)nt * TILE_N
                              + (size_t)bk * LDB + bnh * 64;
        for (int c = 0; c < NC; c++) {
            int s = c - (c / STAGES) * STAGES;
            if (c >= STAGES) NB_SYNC(4 + s);
            char* bb = smem + s * BUF_STRIDE;
            const uint4* ahp = (const uint4*)(ah_row + c * TILE_K);
            const uint4* alp = (const uint4*)(al_row + c * TILE_K);
#pragma unroll
            for (int j = 0; j < 8; j++)
                *(uint4*)(bb + OFF_AH + swA(p, j * 16)) = ahp[j];
#pragma unroll
            for (int j = 0; j < 8; j++)
                *(uint4*)(bb + OFF_AL + swA(p, j * 16)) = alp[j];
            const float4* bp = (const float4*)(bsrc + (size_t)c * TILE_K * LDB);
#pragma unroll
            for (int jj = 0; jj < 8; jj++) {
                float4 a = bp[2 * jj], b = bp[2 * jj + 1];
                uint32_t h0 = pack_hi2(a.x, a.y), h1 = pack_hi2(a.z, a.w);
                uint32_t h2 = pack_hi2(b.x, b.y), h3 = pack_hi2(b.z, b.w);
                uint32_t l0 = pack_lo2(a.x, a.y, h0), l1 = pack_lo2(a.z, a.w, h1);
                uint32_t l2 = pack_lo2(b.x, b.y, h2), l3 = pack_lo2(b.z, b.w, h3);
                uint32_t off = swB(bk, bnh * 128 + jj * 16);
                *(uint4*)(bb + OFF_BH + off) = make_uint4(h0, h1, h2, h3);
                *(uint4*)(bb + OFF_BL + off) = make_uint4(l0, l1, l2, l3);
            }
            NB_ARRIVE(1 + s);
        }
    } else {
        // ---------------- consumer ----------------
        int wm = wid >> 1, wn = wid & 1;
        float acc[4][8][4];
#pragma unroll
        for (int mi = 0; mi < 4; mi++)
#pragma unroll
            for (int nj = 0; nj < 8; nj++)
#pragma unroll
                for (int q = 0; q < 4; q++) acc[mi][nj][q] = 0.f;

        for (int c = 0; c < NC; c++) {
            int s = c - (c / STAGES) * STAGES;
            NB_SYNC(1 + s);
            consumer_chunk(sbase + s * BUF_STRIDE, wm, wn, lane, acc);
            NB_ARRIVE(4 + s);
        }

        int r0 = rbase + wm * 64 + (lane >> 2);
        int c0 = nt * TILE_N + wn * 64 + (lane & 3) * 2;
#pragma unroll
        for (int mi = 0; mi < 4; mi++) {
#pragma unroll
            for (int nj = 0; nj < 8; nj++) {
                int col = c0 + (nj >> 1) * 16 + (nj & 1) * 8;
#pragma unroll
                for (int h = 0; h < 2; h++) {
                    int row = r0 + mi * 16 + h * 8;
                    if (IS_FFN1) {
                        float v0 = gelu_ex(acc[mi][nj][2 * h]);
                        float v1 = gelu_ex(acc[mi][nj][2 * h + 1]);
                        uint32_t hb = pack_hi2(v0, v1);
                        uint32_t lb = pack_lo2(v0, v1, hb);
                        size_t idx = (size_t)row * FFN + col;
                        *(uint32_t*)(g_Hh + idx) = hb;
                        *(uint32_t*)(g_Hl + idx) = lb;
                    } else {
                        *(float2*)(g_Y + (size_t)row * HID + col) =
                            make_float2(acc[mi][nj][2 * h], acc[mi][nj][2 * h + 1]);
                    }
                }
            }
        }
    }
}

// ---------------- combine ----------------------------------------------------
__global__ void combine_kernel(float* __restrict__ out) {
    int n = blockIdx.x;
    int h4 = threadIdx.x * 4;
    if (h4 >= HID) return;
    int   r0 = g_slot_row[2 * n],  r1 = g_slot_row[2 * n + 1];
    float g0 = g_slot_gate[2 * n], g1 = g_slot_gate[2 * n + 1];
    float4 a = *(const float4*)(g_Y + (size_t)r0 * HID + h4);
    float4 b = *(const float4*)(g_Y + (size_t)r1 * HID + h4);
    float4 o;
    o.x = g0 * a.x + g1 * b.x;
    o.y = g0 * a.y + g1 * b.y;
    o.z = g0 * a.z + g1 * b.z;
    o.w = g0 * a.w + g1 * b.w;
    *(float4*)(out + (size_t)n * HID + h4) = o;
}

// ---------------- launch -----------------------------------------------------
extern "C" void kernel_launch(void* const* d_in, const int* in_sizes, int n_in,
                              void* d_out, int out_size) {
    const float* x  = (const float*)d_in[0];
    const float* rw = (const float*)d_in[1];
    const float* w1 = (const float*)d_in[2];
    const float* w2 = (const float*)d_in[3];
    float* out = (float*)d_out;

    static int attr_done = 0;
    if (!attr_done) {
        cudaFuncSetAttribute(ffn_kernel<true>,  cudaFuncAttributeMaxDynamicSharedMemorySize, SMEM_BYTES);
        cudaFuncSetAttribute(ffn_kernel<false>, cudaFuncAttributeMaxDynamicSharedMemorySize, SMEM_BYTES);
        attr_done = 1;
    }

    init_kernel<<<(MAXROWS + 255) / 256, 256>>>();
    router_kernel<<<(NTOK * 32 + 255) / 256, 256>>>(x, rw);
    scan_scatter_kernel<<<1, 256>>>();
    xsplit_kernel<<<MAXROWS, HID / 4>>>(x);
    ffn_kernel<true><<<dim3(MAX_MT, NT1), 256, SMEM_BYTES>>>(w1);
    ffn_kernel<false><<<dim3(MAX_MT, NT2), 256, SMEM_BYTES>>>(w2);
    combine_kernel<<<NTOK, HID / 4>>>(out);
}

// round 5
// speedup vs baseline: 2.5756x; 2.5756x over previous
#include <cuda_runtime.h>
#include <cuda_fp16.h>
#include <math.h>
#include <stdint.h>

#define NTOK   1024
#define HID    768
#define FFN    3072
#define NEXP   8
#define SLOTS  (NTOK * 2)
#define TILE_M 128
#define TILE_N 128
#define TILE_K 64
#define MAXROWS 3072
#define MAX_MT (MAXROWS / TILE_M)   // 24
#define NT1    (FFN / TILE_N)       // 24
#define NT2    (HID / TILE_N)       // 6

// per-buffer: A 16K | B 16K ; two buffers = 64 KB -> 2 CTAs/SM
#define OFF_A   0
#define OFF_B   16384
#define BUF_STRIDE 32768
#define SMEM_BYTES (2 * BUF_STRIDE)

// ---------------- scratch ----------------------------------------------------
__device__ int   g_count[NEXP];
__device__ int   g_off[NEXP + 1];
__device__ int   g_tile_expert[MAX_MT];
__device__ int   g_slot_e[SLOTS];
__device__ int   g_slot_pos[SLOTS];
__device__ int   g_slot_row[SLOTS];
__device__ float g_slot_gate[SLOTS];
__device__ int   g_row_token[MAXROWS];
__device__ __half g_Xf[(size_t)MAXROWS * HID];
__device__ __half g_Hf[(size_t)MAXROWS * FFN];
__device__ float  g_Y[(size_t)MAXROWS * HID];

// ---------------- helpers ----------------------------------------------------
__device__ __forceinline__ uint32_t smem_u32(const void* p) {
    uint32_t a;
    asm("{ .reg .u64 t; cvta.to.shared.u64 t, %1; cvt.u32.u64 %0, t; }" : "=r"(a) : "l"(p));
    return a;
}
__device__ __forceinline__ void ldsm_x4(uint32_t* r, uint32_t addr) {
    asm volatile("ldmatrix.sync.aligned.m8n8.x4.shared.b16 {%0,%1,%2,%3}, [%4];"
        : "=r"(r[0]), "=r"(r[1]), "=r"(r[2]), "=r"(r[3]) : "r"(addr));
}
__device__ __forceinline__ void ldsm_x4_t(uint32_t* r, uint32_t addr) {
    asm volatile("ldmatrix.sync.aligned.m8n8.x4.trans.shared.b16 {%0,%1,%2,%3}, [%4];"
        : "=r"(r[0]), "=r"(r[1]), "=r"(r[2]), "=r"(r[3]) : "r"(addr));
}
__device__ __forceinline__ void mma_f16(float* c, const uint32_t* a, uint32_t b0, uint32_t b1) {
    asm volatile("mma.sync.aligned.m16n8k16.row.col.f32.f16.f16.f32 "
        "{%0,%1,%2,%3}, {%4,%5,%6,%7}, {%8,%9}, {%0,%1,%2,%3};"
        : "+f"(c[0]), "+f"(c[1]), "+f"(c[2]), "+f"(c[3])
        : "r"(a[0]), "r"(a[1]), "r"(a[2]), "r"(a[3]), "r"(b0), "r"(b1));
}
__device__ __forceinline__ uint32_t pack2(float f0, float f1) {
    __half2 h = __floats2half2_rn(f0, f1);
    return *reinterpret_cast<uint32_t*>(&h);
}
__device__ __forceinline__ float gelu_ex(float v) {
    return 0.5f * v * (1.f + erff(v * 0.70710678118654752f));
}
// swizzles: A [m][k] 128B rows; B [k][n] 256B rows
__device__ __forceinline__ uint32_t swA(uint32_t m, uint32_t kbyte) {
    return (m * 128 + kbyte) ^ ((m & 7) << 4);
}
__device__ __forceinline__ uint32_t swB(uint32_t k, uint32_t nbyte) {
    return (k * 256 + nbyte) ^ ((k & 7) << 4);
}

// ---------------- init / router / scan+scatter / xconv -----------------------
__global__ void init_kernel() {
    int i = blockIdx.x * blockDim.x + threadIdx.x;
    if (i < MAXROWS) g_row_token[i] = -1;
    if (i < NEXP) g_count[i] = 0;
}

__global__ void router_kernel(const float* __restrict__ x,
                              const float* __restrict__ rw) {
    int gtid = blockIdx.x * blockDim.x + threadIdx.x;
    int tok  = gtid >> 5;
    int lane = gtid & 31;
    if (tok >= NTOK) return;
    const float* xp = x + tok * HID;
    float acc[NEXP];
#pragma unroll
    for (int e = 0; e < NEXP; e++) acc[e] = 0.f;
    for (int i = lane; i < HID; i += 32) {
        float xv = xp[i];
        const float* r = rw + i * NEXP;
#pragma unroll
        for (int e = 0; e < NEXP; e++) acc[e] += xv * r[e];
    }
#pragma unroll
    for (int off = 16; off; off >>= 1)
#pragma unroll
        for (int e = 0; e < NEXP; e++)
            acc[e] += __shfl_xor_sync(0xFFFFFFFFu, acc[e], off);
    if (lane == 0) {
        int i1 = 0; float v1 = acc[0];
#pragma unroll
        for (int e = 1; e < NEXP; e++)
            if (acc[e] > v1) { v1 = acc[e]; i1 = e; }
        int i2 = -1; float v2 = -INFINITY;
#pragma unroll
        for (int e = 0; e < NEXP; e++)
            if (e != i1 && acc[e] > v2) { v2 = acc[e]; i2 = e; }
        float g1 = 1.f / (1.f + expf(v2 - v1));
        float g2 = 1.f - g1;
        int s0 = tok * 2, s1 = s0 + 1;
        g_slot_e[s0] = i1; g_slot_gate[s0] = g1;
        g_slot_pos[s0] = atomicAdd(&g_count[i1], 1);
        g_slot_e[s1] = i2; g_slot_gate[s1] = g2;
        g_slot_pos[s1] = atomicAdd(&g_count[i2], 1);
    }
}

__global__ void scan_scatter_kernel() {
    int t = threadIdx.x;
    if (t == 0) {
        int off = 0;
        for (int e = 0; e < NEXP; e++) {
            g_off[e] = off;
            off += ((g_count[e] + TILE_M - 1) / TILE_M) * TILE_M;
        }
        g_off[NEXP] = off;
    }
    __syncthreads();
    if (t < MAX_MT) {
        int rbase = t * TILE_M;
        int ex = -1;
        for (int e = 0; e < NEXP; e++)
            if (rbase >= g_off[e] && rbase < g_off[e + 1]) { ex = e; break; }
        g_tile_expert[t] = ex;
    }
    for (int s = t; s < SLOTS; s += blockDim.x) {
        int e   = g_slot_e[s];
        int row = g_off[e] + g_slot_pos[s];
        g_slot_row[s]    = row;
        g_row_token[row] = s >> 1;
    }
}

// gather X rows into padded layout as fp16
__global__ void xconv_kernel(const float* __restrict__ x) {
    int row = blockIdx.x;
    int t = threadIdx.x;                 // 192 threads, 4 floats each
    int tok = g_row_token[row];
    float4 v = make_float4(0.f, 0.f, 0.f, 0.f);
    if (tok >= 0) v = ((const float4*)(x + (size_t)tok * HID))[t];
    ((uint2*)(g_Xf + (size_t)row * HID))[t] =
        make_uint2(pack2(v.x, v.y), pack2(v.z, v.w));
}

// ---------------- consumer chunk: warp tile 64x32, single fp16 term ----------
__device__ __forceinline__ void compute_chunk(uint32_t b32, int wm, int wn, int lane,
                                              float acc[4][4][4]) {
    uint32_t aA = b32 + OFF_A, aB = b32 + OFF_B;
    uint32_t a_row = wm * 64 + (lane & 15);
    uint32_t a_kc  = (lane >> 4) * 16;
    uint32_t b_k   = (lane & 7) + ((lane >> 3) & 1) * 8;
    uint32_t b_nc  = (lane >> 4) * 16;
#pragma unroll
    for (int ks = 0; ks < 4; ks++) {
        uint32_t k0 = ks * 16;
        uint32_t ah[4][4], bh[2][4];
#pragma unroll
        for (int mi = 0; mi < 4; mi++)
            ldsm_x4(ah[mi], aA + swA(a_row + mi * 16, k0 * 2 + a_kc));
#pragma unroll
        for (int ni = 0; ni < 2; ni++)
            ldsm_x4_t(bh[ni], aB + swB(k0 + b_k, (wn * 32 + ni * 16) * 2 + b_nc));
#pragma unroll
        for (int mi = 0; mi < 4; mi++)
#pragma unroll
            for (int nj = 0; nj < 4; nj++) {
                int ni = nj >> 1, p = (nj & 1) * 2;
                mma_f16(acc[mi][nj], ah[mi], bh[ni][p], bh[ni][p + 1]);
            }
    }
}

// ---------------- grouped GEMM (fp16 single-pass) ----------------------------
template <bool IS_FFN1>
__global__ void __launch_bounds__(256, 2) ffn_kernel(const float* __restrict__ w) {
    int mt = blockIdx.x, nt = blockIdx.y;
    int e = g_tile_expert[mt];
    if (e < 0) return;

    extern __shared__ char smem[];
    uint32_t sbase = smem_u32(smem);
    int tid = threadIdx.x, wid = tid >> 5, lane = tid & 31;
    int wm = wid >> 2, wn = wid & 3;
    int rbase = mt * TILE_M;

    const int NC  = IS_FFN1 ? (HID / TILE_K) : (FFN / TILE_K);
    const int LDA = IS_FFN1 ? HID : FFN;
    const int LDB = IS_FFN1 ? FFN : HID;

    // A loader: row am, half-row akq (64 halves per thread-pair)
    int am  = tid >> 1;
    int akq = (tid & 1) * 32;
    const __half* arow = (IS_FFN1 ? g_Xf : g_Hf) + (size_t)(rbase + am) * LDA + akq;
    // B loader: k-row bk, 4-col groups at bn + j*16
    int bk = tid >> 2;
    int bn = (tid & 3) * 4;
    const float* bptr = w + (size_t)e * HID * FFN + (size_t)nt * TILE_N
                          + (size_t)bk * LDB + bn;

    float acc[4][4][4];
#pragma unroll
    for (int mi = 0; mi < 4; mi++)
#pragma unroll
        for (int nj = 0; nj < 4; nj++)
#pragma unroll
            for (int q = 0; q < 4; q++) acc[mi][nj][q] = 0.f;

    // prologue: stage chunk 0 into buf 0
    {
        char* bb = smem;
#pragma unroll
        for (int j = 0; j < 4; j++)
            *(uint4*)(bb + OFF_A + swA(am, (akq + j * 8) * 2)) =
                *(const uint4*)(arow + j * 8);
#pragma unroll
        for (int j = 0; j < 8; j++) {
            float4 v = *(const float4*)(bptr + j * 16);
            *(uint2*)(bb + OFF_B + swB(bk, (bn + j * 16) * 2)) =
                make_uint2(pack2(v.x, v.y), pack2(v.z, v.w));
        }
    }
    __syncthreads();

    for (int c = 0; c < NC; c++) {
        if (c + 1 < NC) {
            // stage chunk c+1 into the other buffer (safe: its readers finished
            // at the barrier ending iteration c-1)
            char* bb = smem + ((c + 1) & 1) * BUF_STRIDE;
            const __half* ap = arow + (c + 1) * TILE_K;
            uint4 a0 = *(const uint4*)(ap);
            uint4 a1 = *(const uint4*)(ap + 8);
            uint4 a2 = *(const uint4*)(ap + 16);
            uint4 a3 = *(const uint4*)(ap + 24);
            const float* bp = bptr + (size_t)(c + 1) * TILE_K * LDB;
            float4 f0 = *(const float4*)(bp);
            float4 f1 = *(const float4*)(bp + 16);
            float4 f2 = *(const float4*)(bp + 32);
            float4 f3 = *(const float4*)(bp + 48);
            float4 f4 = *(const float4*)(bp + 64);
            float4 f5 = *(const float4*)(bp + 80);
            float4 f6 = *(const float4*)(bp + 96);
            float4 f7 = *(const float4*)(bp + 112);
            *(uint4*)(bb + OFF_A + swA(am, (akq + 0) * 2))  = a0;
            *(uint4*)(bb + OFF_A + swA(am, (akq + 8) * 2))  = a1;
            *(uint4*)(bb + OFF_A + swA(am, (akq + 16) * 2)) = a2;
            *(uint4*)(bb + OFF_A + swA(am, (akq + 24) * 2)) = a3;
            *(uint2*)(bb + OFF_B + swB(bk, (bn + 0) * 2))   = make_uint2(pack2(f0.x, f0.y), pack2(f0.z, f0.w));
            *(uint2*)(bb + OFF_B + swB(bk, (bn + 16) * 2))  = make_uint2(pack2(f1.x, f1.y), pack2(f1.z, f1.w));
            *(uint2*)(bb + OFF_B + swB(bk, (bn + 32) * 2))  = make_uint2(pack2(f2.x, f2.y), pack2(f2.z, f2.w));
            *(uint2*)(bb + OFF_B + swB(bk, (bn + 48) * 2))  = make_uint2(pack2(f3.x, f3.y), pack2(f3.z, f3.w));
            *(uint2*)(bb + OFF_B + swB(bk, (bn + 64) * 2))  = make_uint2(pack2(f4.x, f4.y), pack2(f4.z, f4.w));
            *(uint2*)(bb + OFF_B + swB(bk, (bn + 80) * 2))  = make_uint2(pack2(f5.x, f5.y), pack2(f5.z, f5.w));
            *(uint2*)(bb + OFF_B + swB(bk, (bn + 96) * 2))  = make_uint2(pack2(f6.x, f6.y), pack2(f6.z, f6.w));
            *(uint2*)(bb + OFF_B + swB(bk, (bn + 112) * 2)) = make_uint2(pack2(f7.x, f7.y), pack2(f7.z, f7.w));
        }
        compute_chunk(sbase + (c & 1) * BUF_STRIDE, wm, wn, lane, acc);
        __syncthreads();
    }

    // epilogue
    int r0 = rbase + wm * 64 + (lane >> 2);
    int c0 = nt * TILE_N + wn * 32 + (lane & 3) * 2;
#pragma unroll
    for (int mi = 0; mi < 4; mi++) {
#pragma unroll
        for (int nj = 0; nj < 4; nj++) {
            int col = c0 + nj * 8;
#pragma unroll
            for (int h = 0; h < 2; h++) {
                int row = r0 + mi * 16 + h * 8;
                if (IS_FFN1) {
                    float v0 = gelu_ex(acc[mi][nj][2 * h]);
                    float v1 = gelu_ex(acc[mi][nj][2 * h + 1]);
                    *(uint32_t*)(g_Hf + (size_t)row * FFN + col) = pack2(v0, v1);
                } else {
                    *(float2*)(g_Y + (size_t)row * HID + col) =
                        make_float2(acc[mi][nj][2 * h], acc[mi][nj][2 * h + 1]);
                }
            }
        }
    }
}

// ---------------- combine ----------------------------------------------------
__global__ void combine_kernel(float* __restrict__ out) {
    int n = blockIdx.x;
    int h4 = threadIdx.x * 4;
    if (h4 >= HID) return;
    int   r0 = g_slot_row[2 * n],  r1 = g_slot_row[2 * n + 1];
    float g0 = g_slot_gate[2 * n], g1 = g_slot_gate[2 * n + 1];
    float4 a = *(const float4*)(g_Y + (size_t)r0 * HID + h4);
    float4 b = *(const float4*)(g_Y + (size_t)r1 * HID + h4);
    float4 o;
    o.x = g0 * a.x + g1 * b.x;
    o.y = g0 * a.y + g1 * b.y;
    o.z = g0 * a.z + g1 * b.z;
    o.w = g0 * a.w + g1 * b.w;
    *(float4*)(out + (size_t)n * HID + h4) = o;
}

// ---------------- launch -----------------------------------------------------
extern "C" void kernel_launch(void* const* d_in, const int* in_sizes, int n_in,
                              void* d_out, int out_size) {
    const float* x  = (const float*)d_in[0];
    const float* rw = (const float*)d_in[1];
    const float* w1 = (const float*)d_in[2];
    const float* w2 = (const float*)d_in[3];
    float* out = (float*)d_out;

    static int attr_done = 0;
    if (!attr_done) {
        cudaFuncSetAttribute(ffn_kernel<true>,  cudaFuncAttributeMaxDynamicSharedMemorySize, SMEM_BYTES);
        cudaFuncSetAttribute(ffn_kernel<false>, cudaFuncAttributeMaxDynamicSharedMemorySize, SMEM_BYTES);
        attr_done = 1;
    }

    init_kernel<<<(MAXROWS + 255) / 256, 256>>>();
    router_kernel<<<(NTOK * 32 + 255) / 256, 256>>>(x, rw);
    scan_scatter_kernel<<<1, 256>>>();
    xconv_kernel<<<MAXROWS, HID / 4>>>(x);
    ffn_kernel<true><<<dim3(MAX_MT, NT1), 256, SMEM_BYTES>>>(w1);
    ffn_kernel<false><<<dim3(MAX_MT, NT2), 256, SMEM_BYTES>>>(w2);
    combine_kernel<<<NTOK, HID / 4>>>(out);
}

// round 6
// speedup vs baseline: 3.5170x; 1.3655x over previous
#include <cuda_runtime.h>
#include <cuda_fp16.h>
#include <math.h>
#include <stdint.h>

#define NTOK   1024
#define HID    768
#define FFN    3072
#define NEXP   8
#define SLOTS  (NTOK * 2)
#define TILE_M 128
#define TILE_N 128
#define TILE_K 64
#define MAXROWS 3072
#define MAX_MT (MAXROWS / TILE_M)   // 24
#define NT1    (FFN / TILE_N)       // 24
#define NT2    (HID / TILE_N)       // 6
#define W_ELEMS (NEXP * HID * FFN)  // 18874368
#define W_N4    (W_ELEMS / 4)

// per-stage: A 16K | B 16K ; three stages = 96 KB -> 2 CTAs/SM
#define OFF_A   0
#define OFF_B   16384
#define BUF_STRIDE 32768
#define STAGES 3
#define SMEM_BYTES (STAGES * BUF_STRIDE)

// ---------------- scratch ----------------------------------------------------
__device__ int   g_count[NEXP];
__device__ int   g_off[NEXP + 1];
__device__ int   g_tile_expert[MAX_MT];
__device__ int   g_slot_e[SLOTS];
__device__ int   g_slot_pos[SLOTS];
__device__ int   g_slot_row[SLOTS];
__device__ float g_slot_gate[SLOTS];
__device__ int   g_row_token[MAXROWS];
__device__ __align__(16) __half g_Xf[(size_t)MAXROWS * HID];
__device__ __align__(16) __half g_Hf[(size_t)MAXROWS * FFN];
__device__ __align__(16) __half g_W1f[(size_t)W_ELEMS];
__device__ __align__(16) __half g_W2f[(size_t)W_ELEMS];
__device__ __align__(16) float  g_Y[(size_t)MAXROWS * HID];

// ---------------- helpers ----------------------------------------------------
__device__ __forceinline__ uint32_t smem_u32(const void* p) {
    uint32_t a;
    asm("{ .reg .u64 t; cvta.to.shared.u64 t, %1; cvt.u32.u64 %0, t; }" : "=r"(a) : "l"(p));
    return a;
}
__device__ __forceinline__ void cpa16(uint32_t dst, const void* src) {
    asm volatile("cp.async.cg.shared.global [%0], [%1], 16;" :: "r"(dst), "l"(src));
}
__device__ __forceinline__ void cpa_commit() {
    asm volatile("cp.async.commit_group;" ::: "memory");
}
template <int N>
__device__ __forceinline__ void cpa_wait() {
    asm volatile("cp.async.wait_group %0;" :: "n"(N) : "memory");
}
__device__ __forceinline__ void ldsm_x4(uint32_t* r, uint32_t addr) {
    asm volatile("ldmatrix.sync.aligned.m8n8.x4.shared.b16 {%0,%1,%2,%3}, [%4];"
        : "=r"(r[0]), "=r"(r[1]), "=r"(r[2]), "=r"(r[3]) : "r"(addr));
}
__device__ __forceinline__ void ldsm_x4_t(uint32_t* r, uint32_t addr) {
    asm volatile("ldmatrix.sync.aligned.m8n8.x4.trans.shared.b16 {%0,%1,%2,%3}, [%4];"
        : "=r"(r[0]), "=r"(r[1]), "=r"(r[2]), "=r"(r[3]) : "r"(addr));
}
__device__ __forceinline__ void mma_f16(float* c, const uint32_t* a, uint32_t b0, uint32_t b1) {
    asm volatile("mma.sync.aligned.m16n8k16.row.col.f32.f16.f16.f32 "
        "{%0,%1,%2,%3}, {%4,%5,%6,%7}, {%8,%9}, {%0,%1,%2,%3};"
        : "+f"(c[0]), "+f"(c[1]), "+f"(c[2]), "+f"(c[3])
        : "r"(a[0]), "r"(a[1]), "r"(a[2]), "r"(a[3]), "r"(b0), "r"(b1));
}
__device__ __forceinline__ uint32_t pack2(float f0, float f1) {
    __half2 h = __floats2half2_rn(f0, f1);
    return *reinterpret_cast<uint32_t*>(&h);
}
__device__ __forceinline__ float gelu_ex(float v) {
    return 0.5f * v * (1.f + erff(v * 0.70710678118654752f));
}
// swizzles: A [m][k] 128B rows; B [k][n] 256B rows
__device__ __forceinline__ uint32_t swA(uint32_t m, uint32_t kbyte) {
    return (m * 128 + kbyte) ^ ((m & 7) << 4);
}
__device__ __forceinline__ uint32_t swB(uint32_t k, uint32_t nbyte) {
    return (k * 256 + nbyte) ^ ((k & 7) << 4);
}

// ---------------- init / router / scan+scatter / xconv / wconv ---------------
__global__ void init_kernel() {
    int i = blockIdx.x * blockDim.x + threadIdx.x;
    if (i < MAXROWS) g_row_token[i] = -1;
    if (i < NEXP) g_count[i] = 0;
}

__global__ void router_kernel(const float* __restrict__ x,
                              const float* __restrict__ rw) {
    int gtid = blockIdx.x * blockDim.x + threadIdx.x;
    int tok  = gtid >> 5;
    int lane = gtid & 31;
    if (tok >= NTOK) return;
    const float* xp = x + tok * HID;
    float acc[NEXP];
#pragma unroll
    for (int e = 0; e < NEXP; e++) acc[e] = 0.f;
    for (int i = lane; i < HID; i += 32) {
        float xv = xp[i];
        const float* r = rw + i * NEXP;
#pragma unroll
        for (int e = 0; e < NEXP; e++) acc[e] += xv * r[e];
    }
#pragma unroll
    for (int off = 16; off; off >>= 1)
#pragma unroll
        for (int e = 0; e < NEXP; e++)
            acc[e] += __shfl_xor_sync(0xFFFFFFFFu, acc[e], off);
    if (lane == 0) {
        int i1 = 0; float v1 = acc[0];
#pragma unroll
        for (int e = 1; e < NEXP; e++)
            if (acc[e] > v1) { v1 = acc[e]; i1 = e; }
        int i2 = -1; float v2 = -INFINITY;
#pragma unroll
        for (int e = 0; e < NEXP; e++)
            if (e != i1 && acc[e] > v2) { v2 = acc[e]; i2 = e; }
        float g1 = 1.f / (1.f + expf(v2 - v1));
        float g2 = 1.f - g1;
        int s0 = tok * 2, s1 = s0 + 1;
        g_slot_e[s0] = i1; g_slot_gate[s0] = g1;
        g_slot_pos[s0] = atomicAdd(&g_count[i1], 1);
        g_slot_e[s1] = i2; g_slot_gate[s1] = g2;
        g_slot_pos[s1] = atomicAdd(&g_count[i2], 1);
    }
}

__global__ void scan_scatter_kernel() {
    int t = threadIdx.x;
    if (t == 0) {
        int off = 0;
        for (int e = 0; e < NEXP; e++) {
            g_off[e] = off;
            off += ((g_count[e] + TILE_M - 1) / TILE_M) * TILE_M;
        }
        g_off[NEXP] = off;
    }
    __syncthreads();
    if (t < MAX_MT) {
        int rbase = t * TILE_M;
        int ex = -1;
        for (int e = 0; e < NEXP; e++)
            if (rbase >= g_off[e] && rbase < g_off[e + 1]) { ex = e; break; }
        g_tile_expert[t] = ex;
    }
    for (int s = t; s < SLOTS; s += blockDim.x) {
        int e   = g_slot_e[s];
        int row = g_off[e] + g_slot_pos[s];
        g_slot_row[s]    = row;
        g_row_token[row] = s >> 1;
    }
}

// gather X rows into padded layout as fp16
__global__ void xconv_kernel(const float* __restrict__ x) {
    int row = blockIdx.x;
    int t = threadIdx.x;                 // 192 threads, 4 floats each
    int tok = g_row_token[row];
    float4 v = make_float4(0.f, 0.f, 0.f, 0.f);
    if (tok >= 0) v = ((const float4*)(x + (size_t)tok * HID))[t];
    ((uint2*)(g_Xf + (size_t)row * HID))[t] =
        make_uint2(pack2(v.x, v.y), pack2(v.z, v.w));
}

// bulk fp32 -> fp16 weight conversion
__global__ void wconv_kernel(const float4* __restrict__ src, uint2* __restrict__ dst) {
    int i = blockIdx.x * blockDim.x + threadIdx.x;
    int stride = gridDim.x * blockDim.x;
    for (; i < W_N4; i += stride) {
        float4 v = src[i];
        dst[i] = make_uint2(pack2(v.x, v.y), pack2(v.z, v.w));
    }
}

// ---------------- compute chunk: warp tile 64x32, single fp16 term -----------
__device__ __forceinline__ void compute_chunk(uint32_t b32, int wm, int wn, int lane,
                                              float acc[4][4][4]) {
    uint32_t aA = b32 + OFF_A, aB = b32 + OFF_B;
    uint32_t a_row = wm * 64 + (lane & 15);
    uint32_t a_kc  = (lane >> 4) * 16;
    uint32_t b_k   = (lane & 7) + ((lane >> 3) & 1) * 8;
    uint32_t b_nc  = (lane >> 4) * 16;
#pragma unroll
    for (int ks = 0; ks < 4; ks++) {
        uint32_t k0 = ks * 16;
        uint32_t ah[4][4], bh[2][4];
#pragma unroll
        for (int mi = 0; mi < 4; mi++)
            ldsm_x4(ah[mi], aA + swA(a_row + mi * 16, k0 * 2 + a_kc));
#pragma unroll
        for (int ni = 0; ni < 2; ni++)
            ldsm_x4_t(bh[ni], aB + swB(k0 + b_k, (wn * 32 + ni * 16) * 2 + b_nc));
#pragma unroll
        for (int mi = 0; mi < 4; mi++)
#pragma unroll
            for (int nj = 0; nj < 4; nj++) {
                int ni = nj >> 1, p = (nj & 1) * 2;
                mma_f16(acc[mi][nj], ah[mi], bh[ni][p], bh[ni][p + 1]);
            }
    }
}

// ---------------- grouped GEMM (fp16, cp.async 3-stage) ----------------------
template <bool IS_FFN1>
__global__ void __launch_bounds__(256, 2) ffn_kernel(const __half* __restrict__ wf) {
    int mt = blockIdx.x, nt = blockIdx.y;
    int e = g_tile_expert[mt];
    if (e < 0) return;

    extern __shared__ char smem[];
    uint32_t sbase = smem_u32(smem);
    int tid = threadIdx.x, wid = tid >> 5, lane = tid & 31;
    int wm = wid >> 2, wn = wid & 3;
    int rbase = mt * TILE_M;

    const int NC  = IS_FFN1 ? (HID / TILE_K) : (FFN / TILE_K);
    const int LDA = IS_FFN1 ? HID : FFN;
    const int LDB = IS_FFN1 ? FFN : HID;

    // A loader: row am, 32-half group akq; 4 x 16B per chunk
    int am  = tid >> 1;
    int akq = (tid & 1) * 32;
    const __half* aSrc = (IS_FFN1 ? g_Xf : g_Hf) + (size_t)(rbase + am) * LDA + akq;
    // B loader: k-row bk, 8-half groups at bn8 + j*32; 4 x 16B per chunk
    int bk  = tid >> 2;
    int bn8 = (tid & 3) * 8;
    const __half* bSrc = wf + (size_t)e * HID * FFN + (size_t)nt * TILE_N
                            + (size_t)bk * LDB + bn8;

    // loop-invariant SMEM destinations
    uint32_t aDst[4], bDst[4];
#pragma unroll
    for (int j = 0; j < 4; j++) {
        aDst[j] = OFF_A + swA(am, (akq + j * 8) * 2);
        bDst[j] = OFF_B + swB(bk, (bn8 + j * 32) * 2);
    }

    float acc[4][4][4];
#pragma unroll
    for (int mi = 0; mi < 4; mi++)
#pragma unroll
        for (int nj = 0; nj < 4; nj++)
#pragma unroll
            for (int q = 0; q < 4; q++) acc[mi][nj][q] = 0.f;

#define ISSUE(c, s) do {                                                    \
        uint32_t base_ = sbase + (s) * BUF_STRIDE;                          \
        const __half* ap_ = aSrc + (c) * TILE_K;                            \
        const __half* bp_ = bSrc + (size_t)(c) * TILE_K * LDB;              \
        cpa16(base_ + aDst[0], ap_);                                        \
        cpa16(base_ + aDst[1], ap_ + 8);                                    \
        cpa16(base_ + aDst[2], ap_ + 16);                                   \
        cpa16(base_ + aDst[3], ap_ + 24);                                   \
        cpa16(base_ + bDst[0], bp_);                                        \
        cpa16(base_ + bDst[1], bp_ + 32);                                   \
        cpa16(base_ + bDst[2], bp_ + 64);                                   \
        cpa16(base_ + bDst[3], bp_ + 96);                                   \
        cpa_commit();                                                       \
    } while (0)

    ISSUE(0, 0);
    ISSUE(1, 1);

    int s = 0;   // stage of chunk c (c % 3, tracked incrementally)
    for (int c = 0; c < NC; c++) {
        if (c == NC - 1) cpa_wait<0>(); else cpa_wait<1>();
        __syncthreads();
        if (c + 2 < NC) {
            int s2 = s + 2 - (s >= 1 ? STAGES : 0);  // (c+2) % 3
            ISSUE(c + 2, s2);
        }
        compute_chunk(sbase + s * BUF_STRIDE, wm, wn, lane, acc);
        if (++s == STAGES) s = 0;
    }
#undef ISSUE

    // epilogue
    int r0 = rbase + wm * 64 + (lane >> 2);
    int c0 = nt * TILE_N + wn * 32 + (lane & 3) * 2;
#pragma unroll
    for (int mi = 0; mi < 4; mi++) {
#pragma unroll
        for (int nj = 0; nj < 4; nj++) {
            int col = c0 + nj * 8;
#pragma unroll
            for (int h = 0; h < 2; h++) {
                int row = r0 + mi * 16 + h * 8;
                if (IS_FFN1) {
                    float v0 = gelu_ex(acc[mi][nj][2 * h]);
                    float v1 = gelu_ex(acc[mi][nj][2 * h + 1]);
                    *(uint32_t*)(g_Hf + (size_t)row * FFN + col) = pack2(v0, v1);
                } else {
                    *(float2*)(g_Y + (size_t)row * HID + col) =
                        make_float2(acc[mi][nj][2 * h], acc[mi][nj][2 * h + 1]);
                }
            }
        }
    }
}

// ---------------- combine ----------------------------------------------------
__global__ void combine_kernel(float* __restrict__ out) {
    int n = blockIdx.x;
    int h4 = threadIdx.x * 4;
    if (h4 >= HID) return;
    int   r0 = g_slot_row[2 * n],  r1 = g_slot_row[2 * n + 1];
    float g0 = g_slot_gate[2 * n], g1 = g_slot_gate[2 * n + 1];
    float4 a = *(const float4*)(g_Y + (size_t)r0 * HID + h4);
    float4 b = *(const float4*)(g_Y + (size_t)r1 * HID + h4);
    float4 o;
    o.x = g0 * a.x + g1 * b.x;
    o.y = g0 * a.y + g1 * b.y;
    o.z = g0 * a.z + g1 * b.z;
    o.w = g0 * a.w + g1 * b.w;
    *(float4*)(out + (size_t)n * HID + h4) = o;
}

// ---------------- launch -----------------------------------------------------
extern "C" void kernel_launch(void* const* d_in, const int* in_sizes, int n_in,
                              void* d_out, int out_size) {
    const float* x  = (const float*)d_in[0];
    const float* rw = (const float*)d_in[1];
    const float* w1 = (const float*)d_in[2];
    const float* w2 = (const float*)d_in[3];
    float* out = (float*)d_out;

    static int attr_done = 0;
    if (!attr_done) {
        cudaFuncSetAttribute(ffn_kernel<true>,  cudaFuncAttributeMaxDynamicSharedMemorySize, SMEM_BYTES);
        cudaFuncSetAttribute(ffn_kernel<false>, cudaFuncAttributeMaxDynamicSharedMemorySize, SMEM_BYTES);
        attr_done = 1;
    }

    __half* w1f; cudaGetSymbolAddress((void**)&w1f, g_W1f);
    __half* w2f; cudaGetSymbolAddress((void**)&w2f, g_W2f);

    init_kernel<<<(MAXROWS + 255) / 256, 256>>>();
    router_kernel<<<(NTOK * 32 + 255) / 256, 256>>>(x, rw);
    scan_scatter_kernel<<<1, 256>>>();
    xconv_kernel<<<MAXROWS, HID / 4>>>(x);
    wconv_kernel<<<2368, 256>>>((const float4*)w1, (uint2*)w1f);
    wconv_kernel<<<2368, 256>>>((const float4*)w2, (uint2*)w2f);
    ffn_kernel<true><<<dim3(MAX_MT, NT1), 256, SMEM_BYTES>>>(w1f);
    ffn_kernel<false><<<dim3(MAX_MT, NT2), 256, SMEM_BYTES>>>(w2f);
    combine_kernel<<<NTOK, HID / 4>>>(out);
}